// round 4
// baseline (speedup 1.0000x reference)
#include <cuda_runtime.h>

// Problem constants (fixed shapes per reference)
#define NN   100000
#define EE   1600000
#define FIN  64
#define FOUT 32

// Scratch (static __device__ arrays — no runtime allocation)
__device__ float g_deg[NN];
__device__ float g_dis[NN];
__device__ float g_agg[NN * FOUT];

typedef unsigned long long u64;

__device__ __forceinline__ u64 pk2(float lo, float hi) {
    u64 r; asm("mov.b64 %0, {%1, %2};" : "=l"(r) : "f"(lo), "f"(hi)); return r;
}
__device__ __forceinline__ void upk2(u64 v, float& lo, float& hi) {
    asm("mov.b64 {%0, %1}, %2;" : "=f"(lo), "=f"(hi) : "l"(v));
}
#define FMA2(acc, a, b) asm("fma.rn.f32x2 %0, %1, %2, %0;" : "+l"(acc) : "l"(a), "l"(b))

__device__ __forceinline__ float sigf(float v) {
    return __fdividef(1.f, 1.f + __expf(-v));
}
__device__ __forceinline__ float tanhfast(float v) {
    // tanh(x) = 1 - 2/(e^{2x}+1); abs error ~1e-7, fine for this pipeline
    return 1.f - __fdividef(2.f, __expf(2.f * v) + 1.f);
}

// ---------------------------------------------------------------------------
// Kernel 1: zero scratch (agg [N,32] and deg [N])
// ---------------------------------------------------------------------------
__global__ void k_zero() {
    int t = blockIdx.x * blockDim.x + threadIdx.x;
    const int total4 = (NN * FOUT) / 4;  // 800000 float4
    if (t < total4) reinterpret_cast<float4*>(g_agg)[t] = make_float4(0.f, 0.f, 0.f, 0.f);
    if (t < NN) g_deg[t] = 0.f;
}

// ---------------------------------------------------------------------------
// Kernel 2: degree accumulation (segment_sum of edge_weight by row)
// ---------------------------------------------------------------------------
__global__ void k_deg(const int* __restrict__ row, const float* __restrict__ ew) {
    int e = blockIdx.x * blockDim.x + threadIdx.x;
    if (e < EE) atomicAdd(&g_deg[row[e]], ew[e]);
}

// ---------------------------------------------------------------------------
// Kernel 3: dis = deg > 0 ? rsqrt(deg) : 0
// ---------------------------------------------------------------------------
__global__ void k_dis() {
    int n = blockIdx.x * blockDim.x + threadIdx.x;
    if (n < NN) {
        float d = g_deg[n];
        g_dis[n] = d > 0.f ? rsqrtf(d) : 0.f;
    }
}

// ---------------------------------------------------------------------------
// Kernel 4: SpMM scatter: agg[row] += w_norm * h[col]
// 8 threads per edge, float4 per thread, vector reduction (red.global.add.v4)
// ---------------------------------------------------------------------------
__global__ void k_scatter(const int* __restrict__ row, const int* __restrict__ col,
                          const float* __restrict__ ew, const float* __restrict__ h) {
    int t = blockIdx.x * blockDim.x + threadIdx.x;
    if (t >= EE * 8) return;
    int e = t >> 3;
    int q = t & 7;
    int r = row[e];
    int c = col[e];
    float wn = g_dis[r] * ew[e] * g_dis[c];
    float4 hv = reinterpret_cast<const float4*>(h)[c * 8 + q];
    float* dst = &g_agg[r * FOUT + q * 4];
    asm volatile("red.global.add.v4.f32 [%0], {%1, %2, %3, %4};"
                 :: "l"(dst), "f"(wn * hv.x), "f"(wn * hv.y),
                    "f"(wn * hv.z), "f"(wn * hv.w)
                 : "memory");
}

// ---------------------------------------------------------------------------
// Kernel 5: fused dense + gates + output head.
// One warp = 4 nodes; lane = output feature. Weights packed as float4
// (i,f,c,o per gate) in shared memory. Packed f32x2 FMAs, two accumulators
// per node: (i,f) and (c,o).
// ---------------------------------------------------------------------------
__global__ void __launch_bounds__(256) k_fused(
    const float* __restrict__ x, const float* __restrict__ h,
    const float* __restrict__ cst,
    const float* __restrict__ Wi, const float* __restrict__ bi,
    const float* __restrict__ Ti, const float* __restrict__ cbi,
    const float* __restrict__ Wf, const float* __restrict__ bf,
    const float* __restrict__ Tf, const float* __restrict__ cbf,
    const float* __restrict__ Wc, const float* __restrict__ bc,
    const float* __restrict__ Tc, const float* __restrict__ cbc,
    const float* __restrict__ Wo, const float* __restrict__ bo,
    const float* __restrict__ To, const float* __restrict__ cbo,
    const float* __restrict__ Wl, const float* __restrict__ bl,
    float* __restrict__ out)
{
    extern __shared__ float4 sm4[];
    float4* Wp = sm4;              // [64][32] float4 (Wi,Wf,Wc,Wo)[k][f]
    float4* T0 = sm4 + 2048;       // [32][32] float4 theta0 per gate
    float4* T1 = sm4 + 3072;       // [32][32] float4 theta1 per gate
    float4* B4 = sm4 + 4096;       // [32] combined bias (b_g + cb_g)
    float*  wl = reinterpret_cast<float*>(sm4 + 4128); // [32]

    for (int i = threadIdx.x; i < 2048; i += blockDim.x)
        Wp[i] = make_float4(Wi[i], Wf[i], Wc[i], Wo[i]);
    for (int i = threadIdx.x; i < 1024; i += blockDim.x) {
        T0[i] = make_float4(Ti[i], Tf[i], Tc[i], To[i]);
        T1[i] = make_float4(Ti[1024 + i], Tf[1024 + i], Tc[1024 + i], To[1024 + i]);
    }
    if (threadIdx.x < 32) {
        int f = threadIdx.x;
        B4[f] = make_float4(bi[f] + cbi[f], bf[f] + cbf[f],
                            bc[f] + cbc[f], bo[f] + cbo[f]);
        wl[f] = Wl[f];
    }
    __syncthreads();

    const int lane = threadIdx.x & 31;
    const int nWarps = (gridDim.x * blockDim.x) >> 5;
    const int gw = (blockIdx.x * blockDim.x + threadIdx.x) >> 5;

    const float4 bb = B4[lane];
    const float wlv = wl[lane];
    const float blv = bl[0];

    for (int base = gw * 4; base < NN; base += nWarps * 4) {
        float xa[4], xb[4], hv[4], av[4];
        #pragma unroll
        for (int m = 0; m < 4; m++) {
            int n = min(base + m, NN - 1);
            xa[m] = x[n * 64 + lane];
            xb[m] = x[n * 64 + 32 + lane];
            hv[m] = h[n * 32 + lane];
            av[m] = g_agg[n * 32 + lane];
        }
        u64 aif[4], aco[4];
        #pragma unroll
        for (int m = 0; m < 4; m++) {
            aif[m] = pk2(bb.x, bb.y);
            aco[m] = pk2(bb.z, bb.w);
        }

        // x @ Wcat : k = 0..31 (xa), then 32..63 (xb)
        #pragma unroll 8
        for (int k = 0; k < 32; k++) {
            float4 w = Wp[k * 32 + lane];
            u64 wif = pk2(w.x, w.y), wco = pk2(w.z, w.w);
            #pragma unroll
            for (int m = 0; m < 4; m++) {
                float xk = __shfl_sync(0xffffffffu, xa[m], k);
                u64 x2 = pk2(xk, xk);
                FMA2(aif[m], wif, x2);
                FMA2(aco[m], wco, x2);
            }
        }
        #pragma unroll 8
        for (int k = 0; k < 32; k++) {
            float4 w = Wp[(k + 32) * 32 + lane];
            u64 wif = pk2(w.x, w.y), wco = pk2(w.z, w.w);
            #pragma unroll
            for (int m = 0; m < 4; m++) {
                float xk = __shfl_sync(0xffffffffu, xb[m], k);
                u64 x2 = pk2(xk, xk);
                FMA2(aif[m], wif, x2);
                FMA2(aco[m], wco, x2);
            }
        }

        // + h @ theta0  - agg @ theta1
        #pragma unroll 8
        for (int j = 0; j < 32; j++) {
            float4 t0 = T0[j * 32 + lane];
            float4 t1 = T1[j * 32 + lane];
            u64 t0if = pk2(t0.x, t0.y), t0co = pk2(t0.z, t0.w);
            u64 t1if = pk2(t1.x, t1.y), t1co = pk2(t1.z, t1.w);
            #pragma unroll
            for (int m = 0; m < 4; m++) {
                float hj = __shfl_sync(0xffffffffu, hv[m], j);
                float aj = __shfl_sync(0xffffffffu, av[m], j);
                u64 h2 = pk2(hj, hj);
                u64 na2 = pk2(-aj, -aj);
                FMA2(aif[m], t0if, h2);
                FMA2(aco[m], t0co, h2);
                FMA2(aif[m], t1if, na2);
                FMA2(aco[m], t1co, na2);
            }
        }

        // gates + LSTM + relu + head dot
        #pragma unroll
        for (int m = 0; m < 4; m++) {
            int n = base + m;
            float ip, fp, cp, op;
            upk2(aif[m], ip, fp);
            upk2(aco[m], cp, op);
            float I  = sigf(ip);
            float Fg = sigf(fp);
            float T  = tanhfast(cp);
            float O  = sigf(op);
            int nc = min(n, NN - 1);
            float cv = cst[nc * 32 + lane];
            float C = Fg * cv + I * T;
            float H = O * tanhfast(C);
            float r = fmaxf(H, 0.f) * wlv;
            #pragma unroll
            for (int s = 16; s; s >>= 1)
                r += __shfl_xor_sync(0xffffffffu, r, s);
            if (lane == 0 && n < NN) out[n] = r + blv;
        }
    }
}

// ---------------------------------------------------------------------------
// Launch
// ---------------------------------------------------------------------------
extern "C" void kernel_launch(void* const* d_in, const int* in_sizes, int n_in,
                              void* d_out, int out_size) {
    const float* x  = (const float*)d_in[0];
    const int*   ei = (const int*)d_in[1];
    const float* ew = (const float*)d_in[2];
    const float* h  = (const float*)d_in[3];
    const float* c  = (const float*)d_in[4];
    const float* Wi = (const float*)d_in[5];
    const float* bi = (const float*)d_in[6];
    const float* Ti = (const float*)d_in[7];
    const float* cbi= (const float*)d_in[8];
    const float* Wf = (const float*)d_in[9];
    const float* bf = (const float*)d_in[10];
    const float* Tf = (const float*)d_in[11];
    const float* cbf= (const float*)d_in[12];
    const float* Wc = (const float*)d_in[13];
    const float* bc = (const float*)d_in[14];
    const float* Tc = (const float*)d_in[15];
    const float* cbc= (const float*)d_in[16];
    const float* Wo = (const float*)d_in[17];
    const float* bo = (const float*)d_in[18];
    const float* To = (const float*)d_in[19];
    const float* cbo= (const float*)d_in[20];
    const float* Wl = (const float*)d_in[21];
    const float* bl = (const float*)d_in[22];
    float* out = (float*)d_out;

    const int* row = ei;
    const int* col = ei + EE;

    // 1. zero scratch
    {
        int threads = (NN * FOUT) / 4;  // 800000 covers both arrays
        k_zero<<<(threads + 255) / 256, 256>>>();
    }
    // 2. degree
    k_deg<<<(EE + 255) / 256, 256>>>(row, ew);
    // 3. inverse sqrt degree
    k_dis<<<(NN + 255) / 256, 256>>>();
    // 4. SpMM scatter
    k_scatter<<<(EE * 8 + 255) / 256, 256>>>(row, col, ew, h);
    // 5. fused dense + gates + output
    {
        const int smemBytes = 4128 * 16 + 128;  // 66176
        static bool attrSet = false;
        if (!attrSet) {
            cudaFuncSetAttribute(k_fused,
                                 cudaFuncAttributeMaxDynamicSharedMemorySize,
                                 smemBytes);
            attrSet = true;
        }
        k_fused<<<444, 256, smemBytes>>>(
            x, h, c,
            Wi, bi, Ti, cbi,
            Wf, bf, Tf, cbf,
            Wc, bc, Tc, cbc,
            Wo, bo, To, cbo,
            Wl, bl, out);
    }
}

// round 5
// speedup vs baseline: 1.0036x; 1.0036x over previous
#include <cuda_runtime.h>

// Problem constants (fixed shapes per reference)
#define NN   100000
#define EE   1600000
#define FIN  64
#define FOUT 32

// Scratch (static __device__ arrays — no runtime allocation)
__device__ float g_deg[NN];
__device__ float g_dis[NN];
__device__ float g_agg[NN * FOUT];

typedef unsigned long long u64;

__device__ __forceinline__ u64 pk2(float lo, float hi) {
    u64 r; asm("mov.b64 %0, {%1, %2};" : "=l"(r) : "f"(lo), "f"(hi)); return r;
}
__device__ __forceinline__ void upk2(u64 v, float& lo, float& hi) {
    asm("mov.b64 {%0, %1}, %2;" : "=f"(lo), "=f"(hi) : "l"(v));
}
#define FMA2(acc, a, b) asm("fma.rn.f32x2 %0, %1, %2, %0;" : "+l"(acc) : "l"(a), "l"(b))

__device__ __forceinline__ float sigf(float v) {
    return __fdividef(1.f, 1.f + __expf(-v));
}
__device__ __forceinline__ float tanhfast(float v) {
    // tanh(x) = 1 - 2/(e^{2x}+1); abs error ~1e-7, fine for this pipeline
    return 1.f - __fdividef(2.f, __expf(2.f * v) + 1.f);
}

// ---------------------------------------------------------------------------
// Kernel 1: zero scratch (agg [N,32] and deg [N])
// ---------------------------------------------------------------------------
__global__ void k_zero() {
    int t = blockIdx.x * blockDim.x + threadIdx.x;
    const int total4 = (NN * FOUT) / 4;  // 800000 float4
    if (t < total4) reinterpret_cast<float4*>(g_agg)[t] = make_float4(0.f, 0.f, 0.f, 0.f);
    if (t < NN) g_deg[t] = 0.f;
}

// ---------------------------------------------------------------------------
// Kernel 2: degree accumulation (segment_sum of edge_weight by row)
// ---------------------------------------------------------------------------
__global__ void k_deg(const int* __restrict__ row, const float* __restrict__ ew) {
    int e = blockIdx.x * blockDim.x + threadIdx.x;
    if (e < EE) atomicAdd(&g_deg[row[e]], ew[e]);
}

// ---------------------------------------------------------------------------
// Kernel 3: dis = deg > 0 ? rsqrt(deg) : 0
// ---------------------------------------------------------------------------
__global__ void k_dis() {
    int n = blockIdx.x * blockDim.x + threadIdx.x;
    if (n < NN) {
        float d = g_deg[n];
        g_dis[n] = d > 0.f ? rsqrtf(d) : 0.f;
    }
}

// ---------------------------------------------------------------------------
// Kernel 4: SpMM scatter: agg[row] += w_norm * h[col]
// 8 threads per edge, float4 per thread, vector reduction (red.global.add.v4)
// ---------------------------------------------------------------------------
__global__ void k_scatter(const int* __restrict__ row, const int* __restrict__ col,
                          const float* __restrict__ ew, const float* __restrict__ h) {
    int t = blockIdx.x * blockDim.x + threadIdx.x;
    if (t >= EE * 8) return;
    int e = t >> 3;
    int q = t & 7;
    int r = row[e];
    int c = col[e];
    float wn = g_dis[r] * ew[e] * g_dis[c];
    float4 hv = reinterpret_cast<const float4*>(h)[c * 8 + q];
    float* dst = &g_agg[r * FOUT + q * 4];
    asm volatile("red.global.add.v4.f32 [%0], {%1, %2, %3, %4};"
                 :: "l"(dst), "f"(wn * hv.x), "f"(wn * hv.y),
                    "f"(wn * hv.z), "f"(wn * hv.w)
                 : "memory");
}

// ---------------------------------------------------------------------------
// Kernel 5: fused dense + gates + output head.
// One warp = 4 nodes; lane = output feature. Weights packed as float4
// (i,f,c,o per gate) in shared memory. Packed f32x2 FMAs, two accumulators
// per node: (i,f) and (c,o).
// ---------------------------------------------------------------------------
__global__ void __launch_bounds__(256) k_fused(
    const float* __restrict__ x, const float* __restrict__ h,
    const float* __restrict__ cst,
    const float* __restrict__ Wi, const float* __restrict__ bi,
    const float* __restrict__ Ti, const float* __restrict__ cbi,
    const float* __restrict__ Wf, const float* __restrict__ bf,
    const float* __restrict__ Tf, const float* __restrict__ cbf,
    const float* __restrict__ Wc, const float* __restrict__ bc,
    const float* __restrict__ Tc, const float* __restrict__ cbc,
    const float* __restrict__ Wo, const float* __restrict__ bo,
    const float* __restrict__ To, const float* __restrict__ cbo,
    const float* __restrict__ Wl, const float* __restrict__ bl,
    float* __restrict__ out)
{
    extern __shared__ float4 sm4[];
    float4* Wp = sm4;              // [64][32] float4 (Wi,Wf,Wc,Wo)[k][f]
    float4* T0 = sm4 + 2048;       // [32][32] float4 theta0 per gate
    float4* T1 = sm4 + 3072;       // [32][32] float4 theta1 per gate
    float4* B4 = sm4 + 4096;       // [32] combined bias (b_g + cb_g)
    float*  wl = reinterpret_cast<float*>(sm4 + 4128); // [32]

    for (int i = threadIdx.x; i < 2048; i += blockDim.x)
        Wp[i] = make_float4(Wi[i], Wf[i], Wc[i], Wo[i]);
    for (int i = threadIdx.x; i < 1024; i += blockDim.x) {
        T0[i] = make_float4(Ti[i], Tf[i], Tc[i], To[i]);
        T1[i] = make_float4(Ti[1024 + i], Tf[1024 + i], Tc[1024 + i], To[1024 + i]);
    }
    if (threadIdx.x < 32) {
        int f = threadIdx.x;
        B4[f] = make_float4(bi[f] + cbi[f], bf[f] + cbf[f],
                            bc[f] + cbc[f], bo[f] + cbo[f]);
        wl[f] = Wl[f];
    }
    __syncthreads();

    const int lane = threadIdx.x & 31;
    const int nWarps = (gridDim.x * blockDim.x) >> 5;
    const int gw = (blockIdx.x * blockDim.x + threadIdx.x) >> 5;

    const float4 bb = B4[lane];
    const float wlv = wl[lane];
    const float blv = bl[0];

    for (int base = gw * 4; base < NN; base += nWarps * 4) {
        float xa[4], xb[4], hv[4], av[4];
        #pragma unroll
        for (int m = 0; m < 4; m++) {
            int n = min(base + m, NN - 1);
            xa[m] = x[n * 64 + lane];
            xb[m] = x[n * 64 + 32 + lane];
            hv[m] = h[n * 32 + lane];
            av[m] = g_agg[n * 32 + lane];
        }
        u64 aif[4], aco[4];
        #pragma unroll
        for (int m = 0; m < 4; m++) {
            aif[m] = pk2(bb.x, bb.y);
            aco[m] = pk2(bb.z, bb.w);
        }

        // x @ Wcat : k = 0..31 (xa), then 32..63 (xb)
        #pragma unroll 8
        for (int k = 0; k < 32; k++) {
            float4 w = Wp[k * 32 + lane];
            u64 wif = pk2(w.x, w.y), wco = pk2(w.z, w.w);
            #pragma unroll
            for (int m = 0; m < 4; m++) {
                float xk = __shfl_sync(0xffffffffu, xa[m], k);
                u64 x2 = pk2(xk, xk);
                FMA2(aif[m], wif, x2);
                FMA2(aco[m], wco, x2);
            }
        }
        #pragma unroll 8
        for (int k = 0; k < 32; k++) {
            float4 w = Wp[(k + 32) * 32 + lane];
            u64 wif = pk2(w.x, w.y), wco = pk2(w.z, w.w);
            #pragma unroll
            for (int m = 0; m < 4; m++) {
                float xk = __shfl_sync(0xffffffffu, xb[m], k);
                u64 x2 = pk2(xk, xk);
                FMA2(aif[m], wif, x2);
                FMA2(aco[m], wco, x2);
            }
        }

        // + h @ theta0  - agg @ theta1
        #pragma unroll 8
        for (int j = 0; j < 32; j++) {
            float4 t0 = T0[j * 32 + lane];
            float4 t1 = T1[j * 32 + lane];
            u64 t0if = pk2(t0.x, t0.y), t0co = pk2(t0.z, t0.w);
            u64 t1if = pk2(t1.x, t1.y), t1co = pk2(t1.z, t1.w);
            #pragma unroll
            for (int m = 0; m < 4; m++) {
                float hj = __shfl_sync(0xffffffffu, hv[m], j);
                float aj = __shfl_sync(0xffffffffu, av[m], j);
                u64 h2 = pk2(hj, hj);
                u64 na2 = pk2(-aj, -aj);
                FMA2(aif[m], t0if, h2);
                FMA2(aco[m], t0co, h2);
                FMA2(aif[m], t1if, na2);
                FMA2(aco[m], t1co, na2);
            }
        }

        // gates + LSTM + relu + head dot
        #pragma unroll
        for (int m = 0; m < 4; m++) {
            int n = base + m;
            float ip, fp, cp, op;
            upk2(aif[m], ip, fp);
            upk2(aco[m], cp, op);
            float I  = sigf(ip);
            float Fg = sigf(fp);
            float T  = tanhfast(cp);
            float O  = sigf(op);
            int nc = min(n, NN - 1);
            float cv = cst[nc * 32 + lane];
            float C = Fg * cv + I * T;
            float H = O * tanhfast(C);
            float r = fmaxf(H, 0.f) * wlv;
            #pragma unroll
            for (int s = 16; s; s >>= 1)
                r += __shfl_xor_sync(0xffffffffu, r, s);
            if (lane == 0 && n < NN) out[n] = r + blv;
        }
    }
}

// ---------------------------------------------------------------------------
// Launch
// ---------------------------------------------------------------------------
extern "C" void kernel_launch(void* const* d_in, const int* in_sizes, int n_in,
                              void* d_out, int out_size) {
    const float* x  = (const float*)d_in[0];
    const int*   ei = (const int*)d_in[1];
    const float* ew = (const float*)d_in[2];
    const float* h  = (const float*)d_in[3];
    const float* c  = (const float*)d_in[4];
    const float* Wi = (const float*)d_in[5];
    const float* bi = (const float*)d_in[6];
    const float* Ti = (const float*)d_in[7];
    const float* cbi= (const float*)d_in[8];
    const float* Wf = (const float*)d_in[9];
    const float* bf = (const float*)d_in[10];
    const float* Tf = (const float*)d_in[11];
    const float* cbf= (const float*)d_in[12];
    const float* Wc = (const float*)d_in[13];
    const float* bc = (const float*)d_in[14];
    const float* Tc = (const float*)d_in[15];
    const float* cbc= (const float*)d_in[16];
    const float* Wo = (const float*)d_in[17];
    const float* bo = (const float*)d_in[18];
    const float* To = (const float*)d_in[19];
    const float* cbo= (const float*)d_in[20];
    const float* Wl = (const float*)d_in[21];
    const float* bl = (const float*)d_in[22];
    float* out = (float*)d_out;

    const int* row = ei;
    const int* col = ei + EE;

    // 1. zero scratch
    {
        int threads = (NN * FOUT) / 4;  // 800000 covers both arrays
        k_zero<<<(threads + 255) / 256, 256>>>();
    }
    // 2. degree
    k_deg<<<(EE + 255) / 256, 256>>>(row, ew);
    // 3. inverse sqrt degree
    k_dis<<<(NN + 255) / 256, 256>>>();
    // 4. SpMM scatter
    k_scatter<<<(EE * 8 + 255) / 256, 256>>>(row, col, ew, h);
    // 5. fused dense + gates + output
    {
        const int smemBytes = 4128 * 16 + 128;  // 66176
        static bool attrSet = false;
        if (!attrSet) {
            cudaFuncSetAttribute(k_fused,
                                 cudaFuncAttributeMaxDynamicSharedMemorySize,
                                 smemBytes);
            attrSet = true;
        }
        k_fused<<<444, 256, smemBytes>>>(
            x, h, c,
            Wi, bi, Ti, cbi,
            Wf, bf, Tf, cbf,
            Wc, bc, Tc, cbc,
            Wo, bo, To, cbo,
            Wl, bl, out);
    }
}